// round 16
// baseline (speedup 1.0000x reference)
#include <cuda_runtime.h>
#include <cstdint>

#define D_DIM 64
#define BT 64
#define NT 64
#define TPB 256
#define XSTRIDE 68
#define ASTRIDE 68

__device__ __forceinline__ uint64_t pk2(float lo, float hi) {
    uint64_t r; asm("mov.b64 %0, {%1, %2};" : "=l"(r) : "f"(lo), "f"(hi)); return r;
}
__device__ __forceinline__ void upk2(uint64_t v, float& lo, float& hi) {
    asm("mov.b64 {%0, %1}, %2;" : "=f"(lo), "=f"(hi) : "l"(v));
}
__device__ __forceinline__ uint64_t fma2(uint64_t a, uint64_t b, uint64_t c) {
    uint64_t d; asm("fma.rn.f32x2 %0, %1, %2, %3;" : "=l"(d) : "l"(a), "l"(b), "l"(c)); return d;
}
__device__ __forceinline__ uint64_t mul2(uint64_t a, uint64_t b) {
    uint64_t d; asm("mul.rn.f32x2 %0, %1, %2;" : "=l"(d) : "l"(a), "l"(b)); return d;
}

extern __shared__ float smem_dyn[];

// One 4-dim block: 4 b x 4 n per thread (2 packed n-pairs).
// 4 packed fma-class issues per pair-unit: z, w, s2-accum, p. No unpack,
// no scalar FADDs, no +32 bias (s2 accumulates sum z^2 directly).
__device__ __forceinline__ void do_dblk(const float* __restrict__ xrow,
                                        const float* __restrict__ arow,
                                        const float* __restrict__ brow,
                                        int dblk, uint64_t M1,
                                        uint64_t (&s2)[4][2],
                                        uint64_t (&pacc)[4][2])
{
    float xq[4][4];
    #pragma unroll
    for (int bi = 0; bi < 4; bi++) {
        float4 v = *reinterpret_cast<const float4*>(xrow + bi * XSTRIDE + dblk);
        xq[bi][0] = v.x; xq[bi][1] = v.y; xq[bi][2] = v.z; xq[bi][3] = v.w;
    }
    #pragma unroll
    for (int dd = 0; dd < 4; dd++) {
        const int off = (dblk + dd) * ASTRIDE;
        const ulonglong2 av = *reinterpret_cast<const ulonglong2*>(arow + off);
        const ulonglong2 bv = *reinterpret_cast<const ulonglong2*>(brow + off);
        const uint64_t A[2]  = {av.x, av.y};
        const uint64_t Bv[2] = {bv.x, bv.y};
        #pragma unroll
        for (int bi = 0; bi < 4; bi++) {
            const uint64_t xp = pk2(xq[bi][dd], xq[bi][dd]);
            #pragma unroll
            for (int k = 0; k < 2; k++) {
                uint64_t z = fma2(xp, A[k], Bv[k]);
                s2[bi][k] = fma2(z, z, s2[bi][k]);    // sum z^2 (packed FMA accum)
                uint64_t w = fma2(z, z, M1);          // z^2 - 1
                pacc[bi][k] = mul2(pacc[bi][k], w);   // prod (z^2 - 1)
            }
        }
    }
}

__global__ __launch_bounds__(TPB, 3)
void wavelet_kernel(const float* __restrict__ x,
                    const float* __restrict__ centers,
                    const float* __restrict__ scales,
                    float* __restrict__ out, int N)
{
    float* sx = smem_dyn;                   // [BT][XSTRIDE]
    float* sa = sx + BT * XSTRIDE;          // [D][ASTRIDE]  1/s (d-major)
    float* sb = sa + D_DIM * ASTRIDE;       // [D][ASTRIDE]  -c/s

    const int tid = threadIdx.x;
    const int b0 = blockIdx.x * BT;
    const int n0 = blockIdx.y * NT;

    #pragma unroll 2
    for (int i = tid; i < BT * D_DIM; i += TPB) {
        int r = i >> 6, c = i & 63;
        sx[r * XSTRIDE + c] = x[(b0 + r) * D_DIM + c];
    }
    #pragma unroll 4
    for (int i = tid; i < NT * D_DIM; i += TPB) {
        int d = i & 63, n = i >> 6;
        int g = (n0 + n) * D_DIM + d;
        float inv = 1.0f / scales[g];
        sa[d * ASTRIDE + n] = inv;
        sb[d * ASTRIDE + n] = -centers[g] * inv;
    }
    __syncthreads();

    const int ng = tid & 15;           // 4 n's at ng*4
    const int bg = tid >> 4;           // 4 b's at bg*4
    const int rot = (tid >> 5) & 7;    // warp desync (R13)

    const float* xrow = sx + (bg * 4) * XSTRIDE;
    const float* arow = sa + ng * 4;
    const float* brow = sb + ng * 4;

    const uint64_t M1 = pk2(-1.0f, -1.0f);
    uint64_t s2[4][2], pacc[4][2];
    #pragma unroll
    for (int bi = 0; bi < 4; bi++)
        #pragma unroll
        for (int k = 0; k < 2; k++) {
            s2[bi][k]   = pk2(0.f, 0.f);
            pacc[bi][k] = pk2(1.f, 1.f);
        }

    // first half: d = 0..31, warp-rotated block order
    #pragma unroll 2
    for (int q = 0; q < 8; q++)
        do_dblk(xrow, arow, brow, ((q + rot) & 7) * 4, M1, s2, pacc);

    // range-control fold: Gaussian factor for first 32 dims
    #pragma unroll
    for (int bi = 0; bi < 4; bi++)
        #pragma unroll
        for (int k = 0; k < 2; k++) {
            float p0, p1, t0, t1;
            upk2(pacc[bi][k], p0, p1);
            upk2(s2[bi][k],  t0, t1);
            p0 *= __expf(-0.5f * t0);
            p1 *= __expf(-0.5f * t1);
            pacc[bi][k] = pk2(p0, p1);
            s2[bi][k]   = pk2(0.f, 0.f);
        }

    // second half: d = 32..63
    #pragma unroll 2
    for (int q = 0; q < 8; q++)
        do_dblk(xrow, arow, brow, 32 + ((q + rot) & 7) * 4, M1, s2, pacc);

    // epilogue
    float* orow = out + (long)(b0 + bg * 4) * N + n0 + ng * 4;
    #pragma unroll
    for (int bi = 0; bi < 4; bi++) {
        float h[4];
        #pragma unroll
        for (int k = 0; k < 2; k++) {
            float p0, p1, t0, t1;
            upk2(pacc[bi][k], p0, p1);
            upk2(s2[bi][k],  t0, t1);
            h[2 * k]     = p0 * __expf(-0.5f * t0);
            h[2 * k + 1] = p1 * __expf(-0.5f * t1);
        }
        float4 v = {h[0], h[1], h[2], h[3]};
        *reinterpret_cast<float4*>(orow + (long)bi * N) = v;
    }
}

extern "C" void kernel_launch(void* const* d_in, const int* in_sizes, int n_in,
                              void* d_out, int out_size)
{
    const float* x       = (const float*)d_in[0];
    const float* centers = (const float*)d_in[1];
    const float* scales  = (const float*)d_in[2];
    float* out = (float*)d_out;

    const int B = in_sizes[0] / D_DIM;   // 8192
    const int N = in_sizes[1] / D_DIM;   // 512

    const int smem_bytes = (BT * XSTRIDE + 2 * D_DIM * ASTRIDE) * sizeof(float); // 52224
    static bool attr_set = false;
    if (!attr_set) {
        cudaFuncSetAttribute(wavelet_kernel,
                             cudaFuncAttributeMaxDynamicSharedMemorySize, smem_bytes);
        attr_set = true;
    }

    dim3 grid(B / BT, N / NT);           // (128, 8) = 1024 blocks
    wavelet_kernel<<<grid, TPB, smem_bytes>>>(x, centers, scales, out, N);
}